// round 7
// baseline (speedup 1.0000x reference)
#include <cuda_runtime.h>
#include <cuda_bf16.h>
#include <cstdint>

#define NB 2
#define MID 64
#define BAND 8
#define HS 96
#define HQ 384
#define HQP 385
#define LTOT 576
#define PP 25
#define QW 96
#define QPOS (QW*QW)

// scores GEMM tiling (fused im2col, joint regions, k32 chunks)
#define GM_M 96
#define GM_N 192
#define KHALF 1600
#define KROW 3200
#define SCHUNK 50           // 50 chunks of k32, 3 region-passes each

// scores smem: per stage A 96x128B (hi|lo) + B 192x128B (hi|lo)
#define SC_B 12288
#define SC_STAGE 36864
#define SC_TOTAL (2*SC_STAGE)

// out GEMM (attn x v) tiling
#define G2_M 128
#define G2_N 256
#define AK 1152
#define G2_NCHUNK 27
#define G2_SMA 16384
#define G2_SMB 32768
#define G2_STAGE (G2_SMA + G2_SMB)
#define G2_TOTAL (2*G2_STAGE)

// ---------------- scratch (device globals; no runtime allocation) ------------
__device__ float g_kfea[NB*MID*HS*HS];
__device__ float g_qfea[NB*MID*HQP*HQP];      // padded (row/col 384 = 0)
__device__ float g_vfea[NB*BAND*HS*HS];
__device__ float g_ssq[NB*LTOT];
__device__ float g_scale[NB];
__device__ float g_attn[NB*QPOS*LTOT];        // f32 scores (pre-softmax)
__device__ float g_res[NB*BAND*HQP*HQP];
__device__ __nv_bfloat16 g_B[(size_t)NB*LTOT*KROW];   // keys [n][l][hi1600|lo1600]
__device__ __nv_bfloat16 g_attnb[(size_t)NB*QPOS*AK]; // softmaxed attn bf16 hi|lo
__device__ __nv_bfloat16 g_vb[(size_t)NB*G2_N*AK];    // [n][b*25+p][hi|lo], rows 200..255 = 0
__device__ float g_out2[(size_t)NB*QPOS*G2_N];

__device__ __forceinline__ float lrelu(float v) { return v > 0.f ? v : 0.01f * v; }

__device__ __forceinline__ uint32_t smem_u32(const void* p) {
    uint32_t a;
    asm("{ .reg .u64 t; cvta.to.shared.u64 t, %1; cvt.u32.u64 %0, t; }" : "=r"(a) : "l"(p));
    return a;
}
__device__ __forceinline__ void cp16(uint32_t dst, const void* src) {
    asm volatile("cp.async.cg.shared.global [%0], [%1], 16;" :: "r"(dst), "l"(src));
}
__device__ __forceinline__ void ldsm4(uint32_t* r, uint32_t a) {
    asm volatile("ldmatrix.sync.aligned.m8n8.x4.shared.b16 {%0,%1,%2,%3}, [%4];"
                 : "=r"(r[0]), "=r"(r[1]), "=r"(r[2]), "=r"(r[3]) : "r"(a));
}
__device__ __forceinline__ void mma_bf16(float* c, const uint32_t* a, uint32_t b0, uint32_t b1) {
    asm volatile("mma.sync.aligned.m16n8k16.row.col.f32.bf16.bf16.f32 "
                 "{%0,%1,%2,%3}, {%4,%5,%6,%7}, {%8,%9}, {%0,%1,%2,%3};"
                 : "+f"(c[0]), "+f"(c[1]), "+f"(c[2]), "+f"(c[3])
                 : "r"(a[0]), "r"(a[1]), "r"(a[2]), "r"(a[3]), "r"(b0), "r"(b1));
}
#define SWZB(o) ((o) ^ (((o) >> 3) & 0x70))   // 128B rows

// ---------------- 3x3 conv, 1 -> C channels -----------------------------------
template<int C, int HIN, int HOUT>
__global__ void conv_1toC(const float* __restrict__ in, const float* __restrict__ w,
                          const float* __restrict__ bias, float* __restrict__ out) {
    __shared__ float sw[C*9];
    __shared__ float sb[C];
    int t = threadIdx.x;
    for (int e = t; e < C*9; e += blockDim.x) sw[e] = w[e];
    for (int e = t; e < C;   e += blockDim.x) sb[e] = bias[e];
    __syncthreads();
    int idx = blockIdx.x * blockDim.x + t;
    int n = blockIdx.y;
    if (idx >= HOUT*HOUT) return;
    int y = idx / HOUT, x = idx % HOUT;
    bool inside = (y < HIN) && (x < HIN);
    float v[9];
#pragma unroll
    for (int dy = 0; dy < 3; dy++)
#pragma unroll
        for (int dx = 0; dx < 3; dx++) {
            int yy = y + dy - 1, xx = x + dx - 1;
            v[dy*3+dx] = (inside && yy >= 0 && yy < HIN && xx >= 0 && xx < HIN)
                         ? in[(n*HIN + yy)*HIN + xx] : 0.f;
        }
#pragma unroll 8
    for (int c = 0; c < C; c++) {
        float s = 0.f;
        if (inside) {
            s = sb[c];
#pragma unroll
            for (int k = 0; k < 9; k++) s += v[k] * sw[c*9 + k];
            s = lrelu(s);
        }
        out[((n*C + c)*HOUT + y)*HOUT + x] = s;
    }
}

// ---------------- 3x3 conv, C -> C, all outputs per thread ----------------------
template<int C, int H>
__global__ void conv_CtoC_all(const float* __restrict__ in, const float* __restrict__ w,
                              const float* __restrict__ bias, float* __restrict__ out) {
    __shared__ float sw2[9*C*C];     // [ci*9+k][co]
    __shared__ float sb[C];
    int t = threadIdx.x;
    for (int e = t; e < C*C*9; e += blockDim.x) {
        int co = e / (C*9), rem = e % (C*9);
        sw2[rem*C + co] = w[e];
    }
    for (int e = t; e < C; e += blockDim.x) sb[e] = bias[e];
    __syncthreads();
    int idx = blockIdx.x * blockDim.x + t;
    int n = blockIdx.y;
    if (idx >= H*H) return;
    int y = idx / H, x = idx % H;
    float acc[C];
#pragma unroll
    for (int co = 0; co < C; co++) acc[co] = sb[co];
    for (int ci = 0; ci < C; ci++) {
        const float* ip = in + ((size_t)(n*C + ci))*H*H;
#pragma unroll
        for (int dy = 0; dy < 3; dy++) {
            int yy = y + dy - 1;
            if (yy < 0 || yy >= H) continue;
#pragma unroll
            for (int dx = 0; dx < 3; dx++) {
                int xx = x + dx - 1;
                if (xx < 0 || xx >= H) continue;
                float v = __ldg(&ip[yy*H + xx]);
                const float* wp = &sw2[(ci*9 + dy*3 + dx)*C];
#pragma unroll
                for (int co = 0; co < C; co++) acc[co] += v * wp[co];
            }
        }
    }
#pragma unroll
    for (int co = 0; co < C; co++)
        out[((size_t)(n*C + co)*H + y)*H + x] = lrelu(acc[co]);
}

// ---------------- K patches -> bf16 hi/lo B matrix (fused gather+split) ---------
__global__ void build_b_direct() {
    int n = blockIdx.x >> 6, c = blockIdx.x & 63;
    int l = threadIdx.x;                  // 576
    int py = l / 24, px = l % 24;
    __nv_bfloat16* dst = g_B + ((size_t)(n*LTOT) + l)*KROW + c*PP;
    const float* src = g_kfea + ((size_t)(n*MID + c))*HS*HS;
#pragma unroll
    for (int p = 0; p < PP; p++) {
        int i = p / 5, j = p % 5;
        int sy = 4*py + i - 2; if (sy < 0) sy += 97;
        int sx = 4*px + j - 2; if (sx < 0) sx += 97;
        float v = 0.f;
        if (sy < HS && sx < HS) v = src[sy*HS + sx];
        __nv_bfloat16 h = __float2bfloat16(v);
        dst[p] = h;
        dst[KHALF + p] = __float2bfloat16(v - __bfloat162float(h));
    }
}

// ---------------- V patches straight to bf16 hi/lo -------------------------------
__global__ void gather_v() {
    int bid = blockIdx.x;                 // n*200 + b*25 + p
    int n  = bid / (BAND*PP);
    int bp = bid % (BAND*PP);
    int b  = bp / PP;
    int p  = bp % PP;
    int i  = p / 5, j = p % 5;
    int l  = threadIdx.x;
    int py = l / 24, px = l % 24;
    int sy = 4*py + i - 2; if (sy < 0) sy += 97;
    int sx = 4*px + j - 2; if (sx < 0) sx += 97;
    float v = 0.f;
    if (sy < HS && sx < HS)
        v = g_vfea[((n*BAND + b)*HS + sy)*HS + sx];
    __nv_bfloat16 h = __float2bfloat16(v);
    __nv_bfloat16* dst = g_vb + ((size_t)(n*G2_N) + bp)*AK;
    dst[l] = h;
    dst[LTOT + l] = __float2bfloat16(v - __bfloat162float(h));
}

// ---------------- per-patch ssq from g_B (hi+lo), then max ----------------------
__global__ void ssq_b() {
    __shared__ float red[4];
    int row = blockIdx.x;                 // n*576 + l
    int t = threadIdx.x;                  // 128
    const uint4* rp = reinterpret_cast<const uint4*>(g_B + (size_t)row*KROW);
    float s = 0.f;
    for (int e = t; e < 200; e += 128) {
        uint4 hi = __ldg(&rp[e]);
        uint4 lo = __ldg(&rp[200 + e]);
        const uint32_t* hw = &hi.x;
        const uint32_t* lw = &lo.x;
#pragma unroll
        for (int q = 0; q < 4; q++) {
            float2 fh = __bfloat1622float2(*reinterpret_cast<const __nv_bfloat162*>(&hw[q]));
            float2 fl = __bfloat1622float2(*reinterpret_cast<const __nv_bfloat162*>(&lw[q]));
            float v0 = fh.x + fl.x, v1 = fh.y + fl.y;
            s += v0*v0 + v1*v1;
        }
    }
#pragma unroll
    for (int o = 16; o; o >>= 1) s += __shfl_xor_sync(0xffffffffu, s, o);
    if ((t & 31) == 0) red[t >> 5] = s;
    __syncthreads();
    if (t == 0) g_ssq[row] = red[0] + red[1] + red[2] + red[3];
}

__global__ void max_kernel() {
    __shared__ float red[LTOT];
    int n = blockIdx.x;
    int t = threadIdx.x;
    red[t] = g_ssq[n*LTOT + t];
    __syncthreads();
    if (t < 64) red[t] = fmaxf(red[t], red[t + 512]);
    __syncthreads();
    for (int s = 256; s >= 1; s >>= 1) {
        if (t < s) red[t] = fmaxf(red[t], red[t + s]);
        __syncthreads();
    }
    if (t == 0) g_scale[n] = 10.f / sqrtf(red[0]);
}

// ---------------- scores GEMM: fused im2col + bf16x3, k32 joint chunks ------------
// CTA: oy row (96 queries) x 192 keys. 8 warps 2m x 4n, warp tile 48x48.
// smem row layout: [hi 64B | lo 64B] per 128B row, SW128 swizzle.
__global__ void __launch_bounds__(256, 2) scores_mma() {
    extern __shared__ __align__(1024) char smem[];
    const int t = threadIdx.x, lane = t & 31, wid = t >> 5;
    const int wm = wid >> 2, wn = wid & 3;
    const int ntile = blockIdx.x, oy = blockIdx.y, n = blockIdx.z;
    const uint32_t sb = smem_u32(smem);

    const float* Qn = g_qfea + (size_t)n*MID*HQP*HQP + (4*oy)*HQP;
    const __nv_bfloat16* Bb = g_B + ((size_t)n*LTOT + ntile*GM_N)*KROW;

    float acc[3][6][4];
#pragma unroll
    for (int a = 0; a < 3; a++)
#pragma unroll
        for (int b = 0; b < 6; b++)
#pragma unroll
            for (int c = 0; c < 4; c++) acc[a][b][c] = 0.f;

    auto stage = [&](int kr, int s) {
        char* base = smem + s*SC_STAGE;
        int k0 = kr*32;
        // A: 96 m x 16 k-pairs; hi at byte kp*4, lo at 64+kp*4
#pragma unroll
        for (int it = 0; it < 6; it++) {
            int idx = it*256 + t;
            int m  = idx >> 4;
            int kp = idx & 15;
            int k = k0 + kp*2;
            int c = (k*41944) >> 20;      // k/25 (exact for k<1600)
            int p = k - c*25;
            int i = (p*205) >> 10;        // p/5
            int j = p - i*5;
            float v0 = __ldg(&Qn[((size_t)c*HQP + i)*HQP + 4*m + j]);
            k++;
            c = (k*41944) >> 20;
            p = k - c*25;
            i = (p*205) >> 10;
            j = p - i*5;
            float v1 = __ldg(&Qn[((size_t)c*HQP + i)*HQP + 4*m + j]);
            __nv_bfloat16 h0 = __float2bfloat16(v0);
            __nv_bfloat16 h1 = __float2bfloat16(v1);
            __nv_bfloat16 l0 = __float2bfloat16(v0 - __bfloat162float(h0));
            __nv_bfloat16 l1 = __float2bfloat16(v1 - __bfloat162float(h1));
            uint32_t hp = (uint32_t)__bfloat16_as_ushort(h0) |
                          ((uint32_t)__bfloat16_as_ushort(h1) << 16);
            uint32_t lp = (uint32_t)__bfloat16_as_ushort(l0) |
                          ((uint32_t)__bfloat16_as_ushort(l1) << 16);
            *reinterpret_cast<uint32_t*>(base + SWZB((uint32_t)m*128 + kp*4))      = hp;
            *reinterpret_cast<uint32_t*>(base + SWZB((uint32_t)m*128 + 64 + kp*4)) = lp;
        }
        // B: 192 rows; cols 0-3 = hi 16B chunks, 4-7 = lo
        uint32_t bbase = sb + s*SC_STAGE + SC_B;
#pragma unroll
        for (int e = 0; e < 6; e++) {
            int idx = t + e*256;
            int row = idx >> 3, col = idx & 7;
            const __nv_bfloat16* rp = (col < 4)
                ? Bb + (size_t)row*KROW + k0 + col*8
                : Bb + (size_t)row*KROW + KHALF + k0 + (col-4)*8;
            cp16(bbase + SWZB((uint32_t)row*128 + col*16), rp);
        }
        asm volatile("cp.async.commit_group;");
    };

    stage(0, 0);
    asm volatile("cp.async.wait_group 0;");
    __syncthreads();

    for (int kk = 0; kk < SCHUNK; kk++) {
        int s = kk & 1;
        if (kk < SCHUNK-1) stage(kk + 1, s ^ 1);

        uint32_t Ab = sb + s*SC_STAGE;
        uint32_t Bbs = sb + s*SC_STAGE + SC_B;
#pragma unroll
        for (int reg = 0; reg < 3; reg++) {
            uint32_t aoff = (reg == 1) ? 64u : 0u;
            uint32_t boff = (reg == 2) ? 64u : 0u;
#pragma unroll
            for (int st = 0; st < 2; st++) {
                uint32_t col = st*32 + (lane >> 4)*16;
                uint32_t a[3][4];
#pragma unroll
                for (int mi = 0; mi < 3; mi++) {
                    uint32_t row = wm*48 + mi*16 + (lane & 15);
                    ldsm4(a[mi], Ab + SWZB(row*128 + aoff + col));
                }
                uint32_t b[3][4];
#pragma unroll
                for (int nj = 0; nj < 3; nj++) {
                    uint32_t row = wn*48 + nj*16 + (lane & 15);
                    ldsm4(b[nj], Bbs + SWZB(row*128 + boff + col));
                }
#pragma unroll
                for (int mi = 0; mi < 3; mi++)
#pragma unroll
                    for (int ni = 0; ni < 6; ni++) {
                        int nj = ni >> 1;
                        if (ni & 1) mma_bf16(acc[mi][ni], a[mi], b[nj][1], b[nj][3]);
                        else        mma_bf16(acc[mi][ni], a[mi], b[nj][0], b[nj][2]);
                    }
            }
        }
        if (kk < SCHUNK-1) asm volatile("cp.async.wait_group 0;");
        __syncthreads();
    }

    // epilogue
    int mbase = oy*QW + wm*48 + (lane >> 2);
    int nbase = ntile*GM_N + wn*48 + (lane & 3)*2;
#pragma unroll
    for (int mi = 0; mi < 3; mi++)
#pragma unroll
        for (int ni = 0; ni < 6; ni++) {
            int m0 = mbase + mi*16;
            int nc = nbase + ni*8;
            float* r0 = g_attn + ((size_t)n*QPOS + m0)*LTOT + nc;
            float* r1 = r0 + 8*LTOT;
            *reinterpret_cast<float2*>(r0) = make_float2(acc[mi][ni][0], acc[mi][ni][1]);
            *reinterpret_cast<float2*>(r1) = make_float2(acc[mi][ni][2], acc[mi][ni][3]);
        }
}

// ---------------- softmax over 576 keys -> bf16 hi/lo attn -------------------------
__global__ void softmax_kernel() {
    int w    = threadIdx.x >> 5;
    int lane = threadIdx.x & 31;
    int gw = blockIdx.x * 8 + w;
    int n = gw / QPOS;
    float scale = g_scale[n];
    const float* row = g_attn + (size_t)gw * LTOT;
    __nv_bfloat16* rowb = g_attnb + (size_t)gw * AK;
    float v[18];
    float m = -1e30f;
#pragma unroll
    for (int k = 0; k < 18; k++) {
        v[k] = row[lane + 32*k] * scale;
        m = fmaxf(m, v[k]);
    }
#pragma unroll
    for (int o = 16; o; o >>= 1) m = fmaxf(m, __shfl_xor_sync(0xffffffffu, m, o));
    float s = 0.f;
#pragma unroll
    for (int k = 0; k < 18; k++) { v[k] = __expf(v[k] - m); s += v[k]; }
#pragma unroll
    for (int o = 16; o; o >>= 1) s += __shfl_xor_sync(0xffffffffu, s, o);
    float inv = 1.f / s;
#pragma unroll
    for (int k = 0; k < 18; k++) {
        float val = v[k] * inv;
        __nv_bfloat16 h = __float2bfloat16(val);
        rowb[lane + 32*k] = h;
        rowb[LTOT + lane + 32*k] = __float2bfloat16(val - __bfloat162float(h));
    }
}

// ---------------- out GEMM: out2[m][200] = attn[m][:] x vb^T ------------------------
__global__ void __launch_bounds__(256, 1) out_mma() {
    extern __shared__ __align__(1024) char smem[];
    const int t = threadIdx.x, lane = t & 31, wid = t >> 5;
    const int wm = wid >> 1, wn = wid & 1;
    const int mtile = blockIdx.x, n = blockIdx.z;
    const uint32_t sb = smem_u32(smem);

    const __nv_bfloat16* Abase = g_attnb + ((size_t)n*QPOS + mtile*G2_M)*AK;
    const __nv_bfloat16* Bbase = g_vb + (size_t)n*G2_N*AK;

    float acc[2][16][4];
#pragma unroll
    for (int a = 0; a < 2; a++)
#pragma unroll
        for (int b = 0; b < 16; b++)
#pragma unroll
            for (int c = 0; c < 4; c++) acc[a][b][c] = 0.f;

    auto issue_chunk = [&](int kk, int s) {
        int ka, kb;
        if (kk < 9)       { ka = kk*64;                kb = kk*64; }
        else if (kk < 18) { ka = LTOT + (kk-9)*64;     kb = (kk-9)*64; }
        else              { ka = (kk-18)*64;           kb = LTOT + (kk-18)*64; }
        uint32_t As = sb + s*G2_STAGE;
        uint32_t Bs = As + G2_SMA;
#pragma unroll
        for (int e = 0; e < 4; e++) {
            int idx = t + e*256;
            int row = idx >> 3, col = idx & 7;
            uint32_t off = (uint32_t)row*128 + col*16;
            cp16(As + SWZB(off), Abase + (size_t)row*AK + ka + col*8);
        }
#pragma unroll
        for (int e = 0; e < 8; e++) {
            int idx = t + e*256;
            int row = idx >> 3, col = idx & 7;
            uint32_t off = (uint32_t)row*128 + col*16;
            cp16(Bs + SWZB(off), Bbase + (size_t)row*AK + kb + col*8);
        }
        asm volatile("cp.async.commit_group;");
    };

    issue_chunk(0, 0);
    asm volatile("cp.async.wait_group 0;");
    __syncthreads();

    for (int kk = 0; kk < G2_NCHUNK; kk++) {
        int s = kk & 1;
        if (kk < G2_NCHUNK-1) issue_chunk(kk + 1, s ^ 1);

        uint32_t As = sb + s*G2_STAGE;
        uint32_t Bs = As + G2_SMA;
#pragma unroll
        for (int st = 0; st < 4; st++) {
            int kbyte = st*32 + (lane >> 4)*16;
            uint32_t a[2][4];
#pragma unroll
            for (int mi = 0; mi < 2; mi++) {
                uint32_t off = (uint32_t)(wm*32 + mi*16 + (lane & 15))*128 + kbyte;
                ldsm4(a[mi], As + SWZB(off));
            }
            uint32_t b[8][4];
#pragma unroll
            for (int nj = 0; nj < 8; nj++) {
                uint32_t off = (uint32_t)(wn*128 + nj*16 + (lane & 15))*128 + kbyte;
                ldsm4(b[nj], Bs + SWZB(off));
            }
#pragma unroll
            for (int mi = 0; mi < 2; mi++)
#pragma unroll
                for (int ni = 0; ni < 16; ni++) {
                    int nj = ni >> 1;
                    if (ni & 1) mma_bf16(acc[mi][ni], a[mi], b[nj][1], b[nj][3]);
                    else        mma_bf16(acc[mi][ni], a[mi], b[nj][0], b[nj][2]);
                }
        }
        if (kk < G2_NCHUNK-1) asm volatile("cp.async.wait_group 0;");
        __syncthreads();
    }

    int mbase = mtile*G2_M + wm*32 + (lane >> 2);
    int nbase = wn*128 + (lane & 3)*2;
#pragma unroll
    for (int mi = 0; mi < 2; mi++)
#pragma unroll
        for (int ni = 0; ni < 16; ni++) {
            int m0 = mbase + mi*16;
            int nc = nbase + ni*8;
            float* r0 = g_out2 + ((size_t)n*QPOS + m0)*G2_N + nc;
            float* r1 = r0 + 8*G2_N;
            *reinterpret_cast<float2*>(r0) = make_float2(acc[mi][ni][0], acc[mi][ni][1]);
            *reinterpret_cast<float2*>(r1) = make_float2(acc[mi][ni][2], acc[mi][ni][3]);
        }
}

// ---------------- scatter: out2 -> res (conv_transpose geometry) --------------------
__global__ void scatter_out() {
    int idx = blockIdx.x * 256 + threadIdx.x;
    int n = blockIdx.y;
    if (idx >= HQP*HQP) return;
    int y = idx / HQP, x = idx % HQP;
    int oyA = y >> 2, iA = y & 3;  bool vA = oyA < QW;
    int oyB = oyA - 1;             bool vB = (iA == 0) && (oyB >= 0);
    int oxA = x >> 2, jA = x & 3;  bool hA = oxA < QW;
    int oxB = oxA - 1;             bool hB = (jA == 0) && (oxB >= 0);

    float acc[BAND];
#pragma unroll
    for (int b = 0; b < BAND; b++) acc[b] = 0.f;

    const float* base = g_out2 + (size_t)n*QPOS*G2_N;
#pragma unroll
    for (int ti = 0; ti < 2; ti++) {
        bool vi = ti ? vB : vA;
        if (!vi) continue;
        int oy = ti ? oyB : oyA;
        int ii = ti ? 4 : iA;
#pragma unroll
        for (int tj = 0; tj < 2; tj++) {
            bool vj = tj ? hB : hA;
            if (!vj) continue;
            int ox = tj ? oxB : oxA;
            int jj = tj ? 4 : jA;
            const float* row = base + (size_t)(oy*QW + ox)*G2_N + ii*5 + jj;
#pragma unroll
            for (int b = 0; b < BAND; b++) acc[b] += __ldg(&row[b*PP]);
        }
    }
#pragma unroll
    for (int b = 0; b < BAND; b++)
        g_res[(((size_t)n*BAND + b)*HQP + y)*HQP + x] = acc[b] * (1.f/6.f);
}

// ---------------- launch -----------------------------------------------------------
extern "C" void kernel_launch(void* const* d_in, const int* in_sizes, int n_in,
                              void* d_out, int out_size) {
    const float* ms   = (const float*)d_in[0];
    const float* pan  = (const float*)d_in[1];
    const float* pan2 = (const float*)d_in[2];
    const float* wq = (const float*)d_in[3];
    const float* bq = (const float*)d_in[4];
    const float* wk = (const float*)d_in[5];
    const float* bk = (const float*)d_in[6];
    const float* wv = (const float*)d_in[7];
    const float* bv = (const float*)d_in[8];
    const float* wr = (const float*)d_in[9];
    const float* br = (const float*)d_in[10];
    float* out = (float*)d_out;

    void* pv;
    cudaGetSymbolAddress(&pv, g_kfea); float* kfea = (float*)pv;
    cudaGetSymbolAddress(&pv, g_qfea); float* qfea = (float*)pv;
    cudaGetSymbolAddress(&pv, g_vfea); float* vfea = (float*)pv;
    cudaGetSymbolAddress(&pv, g_res);  float* res  = (float*)pv;

    cudaFuncSetAttribute(scores_mma, cudaFuncAttributeMaxDynamicSharedMemorySize, SC_TOTAL);
    cudaFuncSetAttribute(out_mma,    cudaFuncAttributeMaxDynamicSharedMemorySize, G2_TOTAL);

    // 1-3: q features, k features, keys bf16
    conv_1toC<MID, HQ, HQP> <<<dim3((HQP*HQP + 255)/256, NB), 256>>>(pan,  wq, bq, qfea);
    conv_1toC<MID, HS, HS>  <<<dim3((HS*HS   + 255)/256, NB), 256>>>(pan2, wk, bk, kfea);
    build_b_direct<<<NB*MID, LTOT>>>();

    // 4: the big one (profiled slot)
    scores_mma<<<dim3(LTOT/GM_N, QW, NB), 256, SC_TOTAL>>>();

    // v features + patches, norm scale
    conv_CtoC_all<BAND, HS><<<dim3((HS*HS + 255)/256, NB), 256>>>(ms, wv, bv, vfea);
    gather_v<<<NB*BAND*PP, LTOT>>>();
    ssq_b<<<NB*LTOT, 128>>>();
    max_kernel<<<NB, LTOT>>>();

    // softmax + output GEMM + scatter
    softmax_kernel<<<NB*QPOS/8, 256>>>();
    out_mma<<<dim3(QPOS/G2_M, 1, NB), 256, G2_TOTAL>>>();
    scatter_out<<<dim3((HQP*HQP + 255)/256, NB), 256>>>();

    // final conv
    conv_CtoC_all<BAND, HQP><<<dim3((HQP*HQP + 255)/256, NB), 256>>>(res, wr, br, out);
}

// round 8
// speedup vs baseline: 1.3792x; 1.3792x over previous
#include <cuda_runtime.h>
#include <cuda_bf16.h>
#include <cstdint>

#define NB 2
#define MID 64
#define BAND 8
#define HS 96
#define HQ 384
#define HQP 385
#define LTOT 576
#define PP 25
#define QW 96
#define QPOS (QW*QW)

// scores GEMM tiling (fused im2col, joint regions, k64 chunks, reg-prefetch A)
#define GM_M 96
#define GM_N 192
#define KHALF 1600
#define KROW 3200
#define SCHUNK 25

// scores smem per stage: Ahi 12K | Alo 12K | Bhi 24K | Blo 24K
#define SC_AHI 0
#define SC_ALO 12288
#define SC_BHI 24576
#define SC_BLO 49152
#define SC_STAGE 73728
#define SC_TOTAL (2*SC_STAGE)

// out GEMM (attn x v) tiling
#define G2_M 128
#define G2_N 256
#define AK 1152
#define G2_NCHUNK 27
#define G2_SMA 16384
#define G2_SMB 32768
#define G2_STAGE (G2_SMA + G2_SMB)
#define G2_TOTAL (2*G2_STAGE)

// ---------------- scratch (device globals; no runtime allocation) ------------
__device__ float g_kfea[NB*MID*HS*HS];
__device__ float g_qfea[NB*MID*HQP*HQP];      // padded (row/col 384 = 0)
__device__ float g_vfea[NB*BAND*HS*HS];
__device__ int   g_maxssq[NB];
__device__ float g_attn[NB*QPOS*LTOT];        // f32 scores (pre-softmax)
__device__ float g_res[NB*BAND*HQP*HQP];
__device__ __nv_bfloat16 g_B[(size_t)NB*LTOT*KROW];   // keys [n][l][hi1600|lo1600]
__device__ __nv_bfloat16 g_attnb[(size_t)NB*QPOS*AK]; // softmaxed attn bf16 hi|lo
__device__ __nv_bfloat16 g_vb[(size_t)NB*G2_N*AK];    // [n][b*25+p][hi|lo]
__device__ float g_out2[(size_t)NB*QPOS*G2_N];

__device__ __forceinline__ float lrelu(float v) { return v > 0.f ? v : 0.01f * v; }

__device__ __forceinline__ uint32_t smem_u32(const void* p) {
    uint32_t a;
    asm("{ .reg .u64 t; cvta.to.shared.u64 t, %1; cvt.u32.u64 %0, t; }" : "=r"(a) : "l"(p));
    return a;
}
__device__ __forceinline__ void cp16(uint32_t dst, const void* src) {
    asm volatile("cp.async.cg.shared.global [%0], [%1], 16;" :: "r"(dst), "l"(src));
}
__device__ __forceinline__ void ldsm4(uint32_t* r, uint32_t a) {
    asm volatile("ldmatrix.sync.aligned.m8n8.x4.shared.b16 {%0,%1,%2,%3}, [%4];"
                 : "=r"(r[0]), "=r"(r[1]), "=r"(r[2]), "=r"(r[3]) : "r"(a));
}
__device__ __forceinline__ void mma_bf16(float* c, const uint32_t* a, uint32_t b0, uint32_t b1) {
    asm volatile("mma.sync.aligned.m16n8k16.row.col.f32.bf16.bf16.f32 "
                 "{%0,%1,%2,%3}, {%4,%5,%6,%7}, {%8,%9}, {%0,%1,%2,%3};"
                 : "+f"(c[0]), "+f"(c[1]), "+f"(c[2]), "+f"(c[3])
                 : "r"(a[0]), "r"(a[1]), "r"(a[2]), "r"(a[3]), "r"(b0), "r"(b1));
}
#define SWZB(o) ((o) ^ (((o) >> 3) & 0x70))   // 128B rows

// ---------------- 3x3 conv, 1 -> C channels -----------------------------------
template<int C, int HIN, int HOUT>
__global__ void conv_1toC(const float* __restrict__ in, const float* __restrict__ w,
                          const float* __restrict__ bias, float* __restrict__ out) {
    __shared__ float sw[C*9];
    __shared__ float sb[C];
    int t = threadIdx.x;
    for (int e = t; e < C*9; e += blockDim.x) sw[e] = w[e];
    for (int e = t; e < C;   e += blockDim.x) sb[e] = bias[e];
    __syncthreads();
    int idx = blockIdx.x * blockDim.x + t;
    int n = blockIdx.y;
    if (idx >= HOUT*HOUT) return;
    int y = idx / HOUT, x = idx % HOUT;
    bool inside = (y < HIN) && (x < HIN);
    float v[9];
#pragma unroll
    for (int dy = 0; dy < 3; dy++)
#pragma unroll
        for (int dx = 0; dx < 3; dx++) {
            int yy = y + dy - 1, xx = x + dx - 1;
            v[dy*3+dx] = (inside && yy >= 0 && yy < HIN && xx >= 0 && xx < HIN)
                         ? in[(n*HIN + yy)*HIN + xx] : 0.f;
        }
#pragma unroll 8
    for (int c = 0; c < C; c++) {
        float s = 0.f;
        if (inside) {
            s = sb[c];
#pragma unroll
            for (int k = 0; k < 9; k++) s += v[k] * sw[c*9 + k];
            s = lrelu(s);
        }
        out[((n*C + c)*HOUT + y)*HOUT + x] = s;
    }
}

// ---------------- 3x3 conv, C -> C, all outputs per thread ----------------------
template<int C, int H>
__global__ void conv_CtoC_all(const float* __restrict__ in, const float* __restrict__ w,
                              const float* __restrict__ bias, float* __restrict__ out) {
    __shared__ float sw2[9*C*C];     // [ci*9+k][co]
    __shared__ float sb[C];
    int t = threadIdx.x;
    for (int e = t; e < C*C*9; e += blockDim.x) {
        int co = e / (C*9), rem = e % (C*9);
        sw2[rem*C + co] = w[e];
    }
    for (int e = t; e < C; e += blockDim.x) sb[e] = bias[e];
    __syncthreads();
    int idx = blockIdx.x * blockDim.x + t;
    int n = blockIdx.y;
    if (idx >= H*H) return;
    int y = idx / H, x = idx % H;
    float acc[C];
#pragma unroll
    for (int co = 0; co < C; co++) acc[co] = sb[co];
    for (int ci = 0; ci < C; ci++) {
        const float* ip = in + ((size_t)(n*C + ci))*H*H;
#pragma unroll
        for (int dy = 0; dy < 3; dy++) {
            int yy = y + dy - 1;
            if (yy < 0 || yy >= H) continue;
#pragma unroll
            for (int dx = 0; dx < 3; dx++) {
                int xx = x + dx - 1;
                if (xx < 0 || xx >= H) continue;
                float v = __ldg(&ip[yy*H + xx]);
                const float* wp = &sw2[(ci*9 + dy*3 + dx)*C];
#pragma unroll
                for (int co = 0; co < C; co++) acc[co] += v * wp[co];
            }
        }
    }
#pragma unroll
    for (int co = 0; co < C; co++)
        out[((size_t)(n*C + co)*H + y)*H + x] = lrelu(acc[co]);
}

// ---------------- K patches -> bf16 hi/lo B matrix (fused gather+split) ---------
__global__ void build_b_direct() {
    if (blockIdx.x == 0 && threadIdx.x < NB) g_maxssq[threadIdx.x] = 0;
    int n = blockIdx.x >> 6, c = blockIdx.x & 63;
    int l = threadIdx.x;                  // 576
    int py = l / 24, px = l % 24;
    __nv_bfloat16* dst = g_B + ((size_t)(n*LTOT) + l)*KROW + c*PP;
    const float* src = g_kfea + ((size_t)(n*MID + c))*HS*HS;
#pragma unroll
    for (int p = 0; p < PP; p++) {
        int i = p / 5, j = p % 5;
        int sy = 4*py + i - 2; if (sy < 0) sy += 97;
        int sx = 4*px + j - 2; if (sx < 0) sx += 97;
        float v = 0.f;
        if (sy < HS && sx < HS) v = src[sy*HS + sx];
        __nv_bfloat16 h = __float2bfloat16(v);
        dst[p] = h;
        dst[KHALF + p] = __float2bfloat16(v - __bfloat162float(h));
    }
}

// ---------------- V patches straight to bf16 hi/lo -------------------------------
__global__ void gather_v() {
    int bid = blockIdx.x;                 // n*200 + b*25 + p
    int n  = bid / (BAND*PP);
    int bp = bid % (BAND*PP);
    int b  = bp / PP;
    int p  = bp % PP;
    int i  = p / 5, j = p % 5;
    int l  = threadIdx.x;
    int py = l / 24, px = l % 24;
    int sy = 4*py + i - 2; if (sy < 0) sy += 97;
    int sx = 4*px + j - 2; if (sx < 0) sx += 97;
    float v = 0.f;
    if (sy < HS && sx < HS)
        v = g_vfea[((n*BAND + b)*HS + sy)*HS + sx];
    __nv_bfloat16 h = __float2bfloat16(v);
    __nv_bfloat16* dst = g_vb + ((size_t)(n*G2_N) + bp)*AK;
    dst[l] = h;
    dst[LTOT + l] = __float2bfloat16(v - __bfloat162float(h));
}

// ---------------- per-patch ssq from g_B (hi+lo) + atomic max ---------------------
__global__ void ssq_b() {
    __shared__ float red[4];
    int row = blockIdx.x;                 // n*576 + l
    int t = threadIdx.x;                  // 128
    const uint4* rp = reinterpret_cast<const uint4*>(g_B + (size_t)row*KROW);
    float s = 0.f;
    for (int e = t; e < 200; e += 128) {
        uint4 hi = __ldg(&rp[e]);
        uint4 lo = __ldg(&rp[200 + e]);
        const uint32_t* hw = &hi.x;
        const uint32_t* lw = &lo.x;
#pragma unroll
        for (int q = 0; q < 4; q++) {
            float2 fh = __bfloat1622float2(*reinterpret_cast<const __nv_bfloat162*>(&hw[q]));
            float2 fl = __bfloat1622float2(*reinterpret_cast<const __nv_bfloat162*>(&lw[q]));
            float v0 = fh.x + fl.x, v1 = fh.y + fl.y;
            s += v0*v0 + v1*v1;
        }
    }
#pragma unroll
    for (int o = 16; o; o >>= 1) s += __shfl_xor_sync(0xffffffffu, s, o);
    if ((t & 31) == 0) red[t >> 5] = s;
    __syncthreads();
    if (t == 0) {
        float tot = red[0] + red[1] + red[2] + red[3];
        atomicMax(&g_maxssq[row / LTOT], __float_as_int(tot));
    }
}

// ---------------- scores GEMM: fused im2col + bf16x3, k64 chunks, reg prefetch ----
// CTA: oy row (96 queries) x 192 keys. 8 warps 2m x 4n, warp tile 48x48.
__global__ void __launch_bounds__(256, 1) scores_mma() {
    extern __shared__ __align__(1024) char smem[];
    const int t = threadIdx.x, lane = t & 31, wid = t >> 5;
    const int wm = wid >> 2, wn = wid & 3;
    const int ntile = blockIdx.x, oy = blockIdx.y, n = blockIdx.z;
    const uint32_t sb = smem_u32(smem);

    const float* Qn = g_qfea + (size_t)n*MID*HQP*HQP + (4*oy)*HQP;
    const __nv_bfloat16* Bb = g_B + ((size_t)n*LTOT + ntile*GM_N)*KROW;

    float acc[3][6][4];
#pragma unroll
    for (int a = 0; a < 3; a++)
#pragma unroll
        for (int b = 0; b < 6; b++)
#pragma unroll
            for (int c = 0; c < 4; c++) acc[a][b][c] = 0.f;

    float pv0[12], pv1[12];

    auto lda = [&](int k, int m) -> float {
        int c = (k*41944) >> 20;      // k/25 (exact for k<1600)
        int p = k - c*25;
        int i = (p*205) >> 10;        // p/5
        int j = p - i*5;
        return __ldg(&Qn[((size_t)c*HQP + i)*HQP + 4*m + j]);
    };
    auto prefetchA = [&](int kk) {
#pragma unroll
        for (int it = 0; it < 12; it++) {
            int idx = it*256 + t;
            int m = idx >> 5, kp = idx & 31;
            int k = kk*64 + kp*2;
            pv0[it] = lda(k, m);
            pv1[it] = lda(k + 1, m);
        }
    };
    auto issueB = [&](int kk, int s) {
        uint32_t bhi = sb + s*SC_STAGE + SC_BHI;
        uint32_t blo = sb + s*SC_STAGE + SC_BLO;
        int k0 = kk*64;
#pragma unroll
        for (int e = 0; e < 6; e++) {
            int idx = t + e*256;
            int row = idx >> 3, col = idx & 7;
            uint32_t off = SWZB((uint32_t)row*128 + col*16);
            const __nv_bfloat16* rp = Bb + (size_t)row*KROW + k0 + col*8;
            cp16(bhi + off, rp);
            cp16(blo + off, rp + KHALF);
        }
        asm volatile("cp.async.commit_group;");
    };
    auto storeA = [&](int s) {
        char* base = smem + s*SC_STAGE;
#pragma unroll
        for (int it = 0; it < 12; it++) {
            int idx = it*256 + t;
            int m = idx >> 5, kp = idx & 31;
            float v0 = pv0[it], v1 = pv1[it];
            __nv_bfloat16 h0 = __float2bfloat16(v0);
            __nv_bfloat16 h1 = __float2bfloat16(v1);
            __nv_bfloat16 l0 = __float2bfloat16(v0 - __bfloat162float(h0));
            __nv_bfloat16 l1 = __float2bfloat16(v1 - __bfloat162float(h1));
            uint32_t hp = (uint32_t)__bfloat16_as_ushort(h0) |
                          ((uint32_t)__bfloat16_as_ushort(h1) << 16);
            uint32_t lp = (uint32_t)__bfloat16_as_ushort(l0) |
                          ((uint32_t)__bfloat16_as_ushort(l1) << 16);
            uint32_t sw = SWZB((uint32_t)m*128 + kp*4);
            *reinterpret_cast<uint32_t*>(base + SC_AHI + sw) = hp;
            *reinterpret_cast<uint32_t*>(base + SC_ALO + sw) = lp;
        }
    };

    // prologue: stage chunk 0
    issueB(0, 0);
    prefetchA(0);
    storeA(0);
    asm volatile("cp.async.wait_group 0;");
    __syncthreads();

    for (int kk = 0; kk < SCHUNK; kk++) {
        int s = kk & 1;
        if (kk < SCHUNK-1) {
            issueB(kk + 1, s ^ 1);     // async B
            prefetchA(kk + 1);         // LDGs in flight; no stall until storeA
        }
#pragma unroll
        for (int reg = 0; reg < 3; reg++) {
            uint32_t Abase = sb + s*SC_STAGE + (reg == 1 ? SC_ALO : SC_AHI);
            uint32_t Bbase = sb + s*SC_STAGE + (reg == 2 ? SC_BLO : SC_BHI);
#pragma unroll
            for (int st = 0; st < 4; st++) {
                uint32_t col = st*32 + (lane >> 4)*16;
                uint32_t a[3][4];
#pragma unroll
                for (int mi = 0; mi < 3; mi++) {
                    uint32_t row = wm*48 + mi*16 + (lane & 15);
                    ldsm4(a[mi], Abase + SWZB(row*128 + col));
                }
                uint32_t b[3][4];
#pragma unroll
                for (int nj = 0; nj < 3; nj++) {
                    uint32_t row = wn*48 + nj*16 + (lane & 15);
                    ldsm4(b[nj], Bbase + SWZB(row*128 + col));
                }
#pragma unroll
                for (int mi = 0; mi < 3; mi++)
#pragma unroll
                    for (int ni = 0; ni < 6; ni++) {
                        int nj = ni >> 1;
                        if (ni & 1) mma_bf16(acc[mi][ni], a[mi], b[nj][1], b[nj][3]);
                        else        mma_bf16(acc[mi][ni], a[mi], b[nj][0], b[nj][2]);
                    }
            }
        }
        if (kk < SCHUNK-1) {
            storeA(s ^ 1);             // LDG latency hidden by the MMA loop above
            asm volatile("cp.async.wait_group 0;");
        }
        __syncthreads();
    }

    // epilogue
    int mbase = oy*QW + wm*48 + (lane >> 2);
    int nbase = ntile*GM_N + wn*48 + (lane & 3)*2;
#pragma unroll
    for (int mi = 0; mi < 3; mi++)
#pragma unroll
        for (int ni = 0; ni < 6; ni++) {
            int m0 = mbase + mi*16;
            int nc = nbase + ni*8;
            float* r0 = g_attn + ((size_t)n*QPOS + m0)*LTOT + nc;
            float* r1 = r0 + 8*LTOT;
            *reinterpret_cast<float2*>(r0) = make_float2(acc[mi][ni][0], acc[mi][ni][1]);
            *reinterpret_cast<float2*>(r1) = make_float2(acc[mi][ni][2], acc[mi][ni][3]);
        }
}

// ---------------- softmax over 576 keys -> bf16 hi/lo attn -------------------------
__global__ void softmax_kernel() {
    int w    = threadIdx.x >> 5;
    int lane = threadIdx.x & 31;
    int gw = blockIdx.x * 8 + w;
    int n = gw / QPOS;
    float scale = 10.f / sqrtf(__int_as_float(g_maxssq[n]));
    const float* row = g_attn + (size_t)gw * LTOT;
    __nv_bfloat16* rowb = g_attnb + (size_t)gw * AK;
    float v[18];
    float m = -1e30f;
#pragma unroll
    for (int k = 0; k < 18; k++) {
        v[k] = row[lane + 32*k] * scale;
        m = fmaxf(m, v[k]);
    }
#pragma unroll
    for (int o = 16; o; o >>= 1) m = fmaxf(m, __shfl_xor_sync(0xffffffffu, m, o));
    float s = 0.f;
#pragma unroll
    for (int k = 0; k < 18; k++) { v[k] = __expf(v[k] - m); s += v[k]; }
#pragma unroll
    for (int o = 16; o; o >>= 1) s += __shfl_xor_sync(0xffffffffu, s, o);
    float inv = 1.f / s;
#pragma unroll
    for (int k = 0; k < 18; k++) {
        float val = v[k] * inv;
        __nv_bfloat16 h = __float2bfloat16(val);
        rowb[lane + 32*k] = h;
        rowb[LTOT + lane + 32*k] = __float2bfloat16(val - __bfloat162float(h));
    }
}

// ---------------- out GEMM: out2[m][200] = attn[m][:] x vb^T ------------------------
__global__ void __launch_bounds__(256, 1) out_mma() {
    extern __shared__ __align__(1024) char smem[];
    const int t = threadIdx.x, lane = t & 31, wid = t >> 5;
    const int wm = wid >> 1, wn = wid & 1;
    const int mtile = blockIdx.x, n = blockIdx.z;
    const uint32_t sb = smem_u32(smem);

    const __nv_bfloat16* Abase = g_attnb + ((size_t)n*QPOS + mtile*G2_M)*AK;
    const __nv_bfloat16* Bbase = g_vb + (size_t)n*G2_N*AK;

    float acc[2][16][4];
#pragma unroll
    for (int a = 0; a < 2; a++)
#pragma unroll
        for (int b = 0; b < 16; b++)
#pragma unroll
            for (int c = 0; c < 4; c++) acc[a][b][c] = 0.f;

    auto issue_chunk = [&](int kk, int s) {
        int ka, kb;
        if (kk < 9)       { ka = kk*64;                kb = kk*64; }
        else if (kk < 18) { ka = LTOT + (kk-9)*64;     kb = (kk-9)*64; }
        else              { ka = (kk-18)*64;           kb = LTOT + (kk-18)*64; }
        uint32_t As = sb + s*G2_STAGE;
        uint32_t Bs = As + G2_SMA;
#pragma unroll
        for (int e = 0; e < 4; e++) {
            int idx = t + e*256;
            int row = idx >> 3, col = idx & 7;
            uint32_t off = (uint32_t)row*128 + col*16;
            cp16(As + SWZB(off), Abase + (size_t)row*AK + ka + col*8);
        }
#pragma unroll
        for (int e = 0; e < 8; e++) {
            int idx = t + e*256;
            int row = idx >> 3, col = idx & 7;
            uint32_t off = (uint32_t)row*128 + col*16;
            cp16(Bs + SWZB(off), Bbase + (size_t)row*AK + kb + col*8);
        }
        asm volatile("cp.async.commit_group;");
    };

    issue_chunk(0, 0);
    asm volatile("cp.async.wait_group 0;");
    __syncthreads();

    for (int kk = 0; kk < G2_NCHUNK; kk++) {
        int s = kk & 1;
        if (kk < G2_NCHUNK-1) issue_chunk(kk + 1, s ^ 1);

        uint32_t As = sb + s*G2_STAGE;
        uint32_t Bs = As + G2_SMA;
#pragma unroll
        for (int st = 0; st < 4; st++) {
            int kbyte = st*32 + (lane >> 4)*16;
            uint32_t a[2][4];
#pragma unroll
            for (int mi = 0; mi < 2; mi++) {
                uint32_t off = (uint32_t)(wm*32 + mi*16 + (lane & 15))*128 + kbyte;
                ldsm4(a[mi], As + SWZB(off));
            }
            uint32_t b[8][4];
#pragma unroll
            for (int nj = 0; nj < 8; nj++) {
                uint32_t off = (uint32_t)(wn*128 + nj*16 + (lane & 15))*128 + kbyte;
                ldsm4(b[nj], Bs + SWZB(off));
            }
#pragma unroll
            for (int mi = 0; mi < 2; mi++)
#pragma unroll
                for (int ni = 0; ni < 16; ni++) {
                    int nj = ni >> 1;
                    if (ni & 1) mma_bf16(acc[mi][ni], a[mi], b[nj][1], b[nj][3]);
                    else        mma_bf16(acc[mi][ni], a[mi], b[nj][0], b[nj][2]);
                }
        }
        if (kk < G2_NCHUNK-1) asm volatile("cp.async.wait_group 0;");
        __syncthreads();
    }

    int mbase = mtile*G2_M + wm*32 + (lane >> 2);
    int nbase = wn*128 + (lane & 3)*2;
#pragma unroll
    for (int mi = 0; mi < 2; mi++)
#pragma unroll
        for (int ni = 0; ni < 16; ni++) {
            int m0 = mbase + mi*16;
            int nc = nbase + ni*8;
            float* r0 = g_out2 + ((size_t)n*QPOS + m0)*G2_N + nc;
            float* r1 = r0 + 8*G2_N;
            *reinterpret_cast<float2*>(r0) = make_float2(acc[mi][ni][0], acc[mi][ni][1]);
            *reinterpret_cast<float2*>(r1) = make_float2(acc[mi][ni][2], acc[mi][ni][3]);
        }
}

// ---------------- scatter: out2 -> res (conv_transpose geometry) --------------------
__global__ void scatter_out() {
    int idx = blockIdx.x * 256 + threadIdx.x;
    int n = blockIdx.y;
    if (idx >= HQP*HQP) return;
    int y = idx / HQP, x = idx % HQP;
    int oyA = y >> 2, iA = y & 3;  bool vA = oyA < QW;
    int oyB = oyA - 1;             bool vB = (iA == 0) && (oyB >= 0);
    int oxA = x >> 2, jA = x & 3;  bool hA = oxA < QW;
    int oxB = oxA - 1;             bool hB = (jA == 0) && (oxB >= 0);

    float acc[BAND];
#pragma unroll
    for (int b = 0; b < BAND; b++) acc[b] = 0.f;

    const float* base = g_out2 + (size_t)n*QPOS*G2_N;
#pragma unroll
    for (int ti = 0; ti < 2; ti++) {
        bool vi = ti ? vB : vA;
        if (!vi) continue;
        int oy = ti ? oyB : oyA;
        int ii = ti ? 4 : iA;
#pragma unroll
        for (int tj = 0; tj < 2; tj++) {
            bool vj = tj ? hB : hA;
            if (!vj) continue;
            int ox = tj ? oxB : oxA;
            int jj = tj ? 4 : jA;
            const float* row = base + (size_t)(oy*QW + ox)*G2_N + ii*5 + jj;
#pragma unroll
            for (int b = 0; b < BAND; b++) acc[b] += __ldg(&row[b*PP]);
        }
    }
#pragma unroll
    for (int b = 0; b < BAND; b++)
        g_res[(((size_t)n*BAND + b)*HQP + y)*HQP + x] = acc[b] * (1.f/6.f);
}

// ---------------- launch -----------------------------------------------------------
extern "C" void kernel_launch(void* const* d_in, const int* in_sizes, int n_in,
                              void* d_out, int out_size) {
    const float* ms   = (const float*)d_in[0];
    const float* pan  = (const float*)d_in[1];
    const float* pan2 = (const float*)d_in[2];
    const float* wq = (const float*)d_in[3];
    const float* bq = (const float*)d_in[4];
    const float* wk = (const float*)d_in[5];
    const float* bk = (const float*)d_in[6];
    const float* wv = (const float*)d_in[7];
    const float* bv = (const float*)d_in[8];
    const float* wr = (const float*)d_in[9];
    const float* br = (const float*)d_in[10];
    float* out = (float*)d_out;

    void* pv;
    cudaGetSymbolAddress(&pv, g_kfea); float* kfea = (float*)pv;
    cudaGetSymbolAddress(&pv, g_qfea); float* qfea = (float*)pv;
    cudaGetSymbolAddress(&pv, g_vfea); float* vfea = (float*)pv;
    cudaGetSymbolAddress(&pv, g_res);  float* res  = (float*)pv;

    cudaFuncSetAttribute(scores_mma, cudaFuncAttributeMaxDynamicSharedMemorySize, SC_TOTAL);
    cudaFuncSetAttribute(out_mma,    cudaFuncAttributeMaxDynamicSharedMemorySize, G2_TOTAL);

    // 1-3: q features, k features, keys bf16
    conv_1toC<MID, HQ, HQP> <<<dim3((HQP*HQP + 255)/256, NB), 256>>>(pan,  wq, bq, qfea);
    conv_1toC<MID, HS, HS>  <<<dim3((HS*HS   + 255)/256, NB), 256>>>(pan2, wk, bk, kfea);
    build_b_direct<<<NB*MID, LTOT>>>();

    // 4: the big one (profiled slot)
    scores_mma<<<dim3(LTOT/GM_N, QW, NB), 256, SC_TOTAL>>>();

    // v features + patches, norm scale
    conv_CtoC_all<BAND, HS><<<dim3((HS*HS + 255)/256, NB), 256>>>(ms, wv, bv, vfea);
    gather_v<<<NB*BAND*PP, LTOT>>>();
    ssq_b<<<NB*LTOT, 128>>>();

    // softmax + output GEMM + scatter
    softmax_kernel<<<NB*QPOS/8, 256>>>();
    out_mma<<<dim3(QPOS/G2_M, 1, NB), 256, G2_TOTAL>>>();
    scatter_out<<<dim3((HQP*HQP + 255)/256, NB), 256>>>();

    // final conv
    conv_CtoC_all<BAND, HQP><<<dim3((HQP*HQP + 255)/256, NB), 256>>>(res, wr, br, out);
}

// round 9
// speedup vs baseline: 1.5185x; 1.1010x over previous
#include <cuda_runtime.h>
#include <cuda_bf16.h>
#include <cstdint>

#define NB 2
#define MID 64
#define BAND 8
#define HS 96
#define HQ 384
#define HQP 385
#define LTOT 576
#define PP 25
#define QW 96
#define QPOS (QW*QW)

// scores GEMM tiling
#define GM_M 96
#define GM_N 192
#define KHALF 1600
#define KROW 3200
#define SCHUNK 25

// scores smem per stage: Ahi 12K | Alo 12K | Bhi 24K | Blo 24K
#define SC_AHI 0
#define SC_ALO 12288
#define SC_BHI 24576
#define SC_BLO 49152
#define SC_STAGE 73728
#define SC_TOTAL (2*SC_STAGE)

// out GEMM (attn x v) tiling
#define G2_M 128
#define G2_N 256
#define AK 1152
#define G2_NCHUNK 27
#define G2_SMA 16384
#define G2_SMB 32768
#define G2_STAGE (G2_SMA + G2_SMB)
#define G2_TOTAL (2*G2_STAGE)

// ---------------- scratch (device globals; no runtime allocation) ------------
__device__ float g_kfea[NB*MID*HS*HS];
__device__ float g_qfea[NB*MID*HQP*HQP];      // padded (row/col 384 = 0)
__device__ float g_vfea[NB*BAND*HS*HS];
__device__ int   g_maxssq[NB];
__device__ float g_attn[NB*QPOS*LTOT];        // f32 scores (pre-softmax)
__device__ float g_res[NB*BAND*HQP*HQP];
__device__ __nv_bfloat16 g_B[(size_t)NB*LTOT*KROW];   // keys [n][l][hi1600|lo1600]
__device__ __nv_bfloat16 g_attnb[(size_t)NB*QPOS*AK]; // softmaxed attn bf16 hi|lo
__device__ __nv_bfloat16 g_vb[(size_t)NB*G2_N*AK];    // [n][b*25+p][hi|lo]
__device__ float g_out2[(size_t)NB*QPOS*G2_N];

__device__ __forceinline__ float lrelu(float v) { return v > 0.f ? v : 0.01f * v; }

__device__ __forceinline__ uint32_t smem_u32(const void* p) {
    uint32_t a;
    asm("{ .reg .u64 t; cvta.to.shared.u64 t, %1; cvt.u32.u64 %0, t; }" : "=r"(a) : "l"(p));
    return a;
}
__device__ __forceinline__ void cp16(uint32_t dst, const void* src) {
    asm volatile("cp.async.cg.shared.global [%0], [%1], 16;" :: "r"(dst), "l"(src));
}
__device__ __forceinline__ void ldsm4(uint32_t* r, uint32_t a) {
    asm volatile("ldmatrix.sync.aligned.m8n8.x4.shared.b16 {%0,%1,%2,%3}, [%4];"
                 : "=r"(r[0]), "=r"(r[1]), "=r"(r[2]), "=r"(r[3]) : "r"(a));
}
__device__ __forceinline__ void mma_bf16(float* c, const uint32_t* a, uint32_t b0, uint32_t b1) {
    asm volatile("mma.sync.aligned.m16n8k16.row.col.f32.bf16.bf16.f32 "
                 "{%0,%1,%2,%3}, {%4,%5,%6,%7}, {%8,%9}, {%0,%1,%2,%3};"
                 : "+f"(c[0]), "+f"(c[1]), "+f"(c[2]), "+f"(c[3])
                 : "r"(a[0]), "r"(a[1]), "r"(a[2]), "r"(a[3]), "r"(b0), "r"(b1));
}
#define SWZB(o) ((o) ^ (((o) >> 3) & 0x70))   // 128B rows

// ---------------- 3x3 conv, 1 -> C channels -----------------------------------
template<int C, int HIN, int HOUT>
__global__ void conv_1toC(const float* __restrict__ in, const float* __restrict__ w,
                          const float* __restrict__ bias, float* __restrict__ out) {
    __shared__ float sw[C*9];
    __shared__ float sb[C];
    int t = threadIdx.x;
    for (int e = t; e < C*9; e += blockDim.x) sw[e] = w[e];
    for (int e = t; e < C;   e += blockDim.x) sb[e] = bias[e];
    __syncthreads();
    int idx = blockIdx.x * blockDim.x + t;
    int n = blockIdx.y;
    if (idx >= HOUT*HOUT) return;
    int y = idx / HOUT, x = idx % HOUT;
    bool inside = (y < HIN) && (x < HIN);
    float v[9];
#pragma unroll
    for (int dy = 0; dy < 3; dy++)
#pragma unroll
        for (int dx = 0; dx < 3; dx++) {
            int yy = y + dy - 1, xx = x + dx - 1;
            v[dy*3+dx] = (inside && yy >= 0 && yy < HIN && xx >= 0 && xx < HIN)
                         ? in[(n*HIN + yy)*HIN + xx] : 0.f;
        }
#pragma unroll 8
    for (int c = 0; c < C; c++) {
        float s = 0.f;
        if (inside) {
            s = sb[c];
#pragma unroll
            for (int k = 0; k < 9; k++) s += v[k] * sw[c*9 + k];
            s = lrelu(s);
        }
        out[((n*C + c)*HOUT + y)*HOUT + x] = s;
    }
}

// ---------------- 3x3 conv, C -> C, all outputs per thread ----------------------
template<int C, int H>
__global__ void conv_CtoC_all(const float* __restrict__ in, const float* __restrict__ w,
                              const float* __restrict__ bias, float* __restrict__ out) {
    __shared__ float sw2[9*C*C];     // [ci*9+k][co]
    __shared__ float sb[C];
    int t = threadIdx.x;
    for (int e = t; e < C*C*9; e += blockDim.x) {
        int co = e / (C*9), rem = e % (C*9);
        sw2[rem*C + co] = w[e];
    }
    for (int e = t; e < C; e += blockDim.x) sb[e] = bias[e];
    __syncthreads();
    int idx = blockIdx.x * blockDim.x + t;
    int n = blockIdx.y;
    if (idx >= H*H) return;
    int y = idx / H, x = idx % H;
    float acc[C];
#pragma unroll
    for (int co = 0; co < C; co++) acc[co] = sb[co];
    for (int ci = 0; ci < C; ci++) {
        const float* ip = in + ((size_t)(n*C + ci))*H*H;
#pragma unroll
        for (int dy = 0; dy < 3; dy++) {
            int yy = y + dy - 1;
            if (yy < 0 || yy >= H) continue;
#pragma unroll
            for (int dx = 0; dx < 3; dx++) {
                int xx = x + dx - 1;
                if (xx < 0 || xx >= H) continue;
                float v = __ldg(&ip[yy*H + xx]);
                const float* wp = &sw2[(ci*9 + dy*3 + dx)*C];
#pragma unroll
                for (int co = 0; co < C; co++) acc[co] += v * wp[co];
            }
        }
    }
#pragma unroll
    for (int co = 0; co < C; co++)
        out[((size_t)(n*C + co)*H + y)*H + x] = lrelu(acc[co]);
}

// ---------------- K patches -> bf16 hi/lo B matrix (fused gather+split) ---------
__global__ void build_b_direct() {
    if (blockIdx.x == 0 && threadIdx.x < NB) g_maxssq[threadIdx.x] = 0;
    int n = blockIdx.x >> 6, c = blockIdx.x & 63;
    int l = threadIdx.x;                  // 576
    int py = l / 24, px = l % 24;
    __nv_bfloat16* dst = g_B + ((size_t)(n*LTOT) + l)*KROW + c*PP;
    const float* src = g_kfea + ((size_t)(n*MID + c))*HS*HS;
#pragma unroll
    for (int p = 0; p < PP; p++) {
        int i = p / 5, j = p % 5;
        int sy = 4*py + i - 2; if (sy < 0) sy += 97;
        int sx = 4*px + j - 2; if (sx < 0) sx += 97;
        float v = 0.f;
        if (sy < HS && sx < HS) v = src[sy*HS + sx];
        __nv_bfloat16 h = __float2bfloat16(v);
        dst[p] = h;
        dst[KHALF + p] = __float2bfloat16(v - __bfloat162float(h));
    }
}

// ---------------- V patches straight to bf16 hi/lo -------------------------------
__global__ void gather_v() {
    int bid = blockIdx.x;                 // n*200 + b*25 + p
    int n  = bid / (BAND*PP);
    int bp = bid % (BAND*PP);
    int b  = bp / PP;
    int p  = bp % PP;
    int i  = p / 5, j = p % 5;
    int l  = threadIdx.x;
    int py = l / 24, px = l % 24;
    int sy = 4*py + i - 2; if (sy < 0) sy += 97;
    int sx = 4*px + j - 2; if (sx < 0) sx += 97;
    float v = 0.f;
    if (sy < HS && sx < HS)
        v = g_vfea[((n*BAND + b)*HS + sy)*HS + sx];
    __nv_bfloat16 h = __float2bfloat16(v);
    __nv_bfloat16* dst = g_vb + ((size_t)(n*G2_N) + bp)*AK;
    dst[l] = h;
    dst[LTOT + l] = __float2bfloat16(v - __bfloat162float(h));
}

// ---------------- per-patch ssq from g_B (hi+lo) + atomic max ---------------------
__global__ void ssq_b() {
    __shared__ float red[4];
    int row = blockIdx.x;                 // n*576 + l
    int t = threadIdx.x;                  // 128
    const uint4* rp = reinterpret_cast<const uint4*>(g_B + (size_t)row*KROW);
    float s = 0.f;
    for (int e = t; e < 200; e += 128) {
        uint4 hi = __ldg(&rp[e]);
        uint4 lo = __ldg(&rp[200 + e]);
        const uint32_t* hw = &hi.x;
        const uint32_t* lw = &lo.x;
#pragma unroll
        for (int q = 0; q < 4; q++) {
            float2 fh = __bfloat1622float2(*reinterpret_cast<const __nv_bfloat162*>(&hw[q]));
            float2 fl = __bfloat1622float2(*reinterpret_cast<const __nv_bfloat162*>(&lw[q]));
            float v0 = fh.x + fl.x, v1 = fh.y + fl.y;
            s += v0*v0 + v1*v1;
        }
    }
#pragma unroll
    for (int o = 16; o; o >>= 1) s += __shfl_xor_sync(0xffffffffu, s, o);
    if ((t & 31) == 0) red[t >> 5] = s;
    __syncthreads();
    if (t == 0) {
        float tot = red[0] + red[1] + red[2] + red[3];
        atomicMax(&g_maxssq[row / LTOT], __float_as_int(tot));
    }
}

// ---------------- scores GEMM: fused im2col + bf16x3, frag-reuse inner loop -------
// CTA: oy row (96 queries) x 192 keys. 8 warps 2m x 4n, warp tile 48x48.
__global__ void __launch_bounds__(256, 1) scores_mma() {
    extern __shared__ __align__(1024) char smem[];
    __shared__ int offs[KHALF];           // im2col offsets (per k)
    const int t = threadIdx.x, lane = t & 31, wid = t >> 5;
    const int wm = wid >> 2, wn = wid & 3;
    const int ntile = blockIdx.x, oy = blockIdx.y, n = blockIdx.z;
    const uint32_t sb = smem_u32(smem);

    const float* Qn = g_qfea + (size_t)n*MID*HQP*HQP + (4*oy)*HQP;
    const __nv_bfloat16* Bb = g_B + ((size_t)n*LTOT + ntile*GM_N)*KROW;

    // offset table
    for (int e = t; e < KHALF; e += 256) {
        int c = e / 25, p = e % 25, i = p / 5, j = p % 5;
        offs[e] = (c*HQP + i)*HQP + j;
    }

    float acc[3][6][4];
#pragma unroll
    for (int a = 0; a < 3; a++)
#pragma unroll
        for (int b = 0; b < 6; b++)
#pragma unroll
            for (int c = 0; c < 4; c++) acc[a][b][c] = 0.f;

    float pv0[6], pv1[6];

    auto prefA = [&](int kk, int half) {
#pragma unroll
        for (int it = 0; it < 6; it++) {
            int idx = (half*6 + it)*256 + t;
            int m = idx >> 5, kp = idx & 31;
            int k = kk*64 + kp*2;
            pv0[it] = __ldg(&Qn[offs[k]   + 4*m]);
            pv1[it] = __ldg(&Qn[offs[k+1] + 4*m]);
        }
    };
    auto storeA = [&](int s, int half) {
        char* base = smem + s*SC_STAGE;
#pragma unroll
        for (int it = 0; it < 6; it++) {
            int idx = (half*6 + it)*256 + t;
            int m = idx >> 5, kp = idx & 31;
            float v0 = pv0[it], v1 = pv1[it];
            __nv_bfloat16 h0 = __float2bfloat16(v0);
            __nv_bfloat16 h1 = __float2bfloat16(v1);
            __nv_bfloat16 l0 = __float2bfloat16(v0 - __bfloat162float(h0));
            __nv_bfloat16 l1 = __float2bfloat16(v1 - __bfloat162float(h1));
            uint32_t hp = (uint32_t)__bfloat16_as_ushort(h0) |
                          ((uint32_t)__bfloat16_as_ushort(h1) << 16);
            uint32_t lp = (uint32_t)__bfloat16_as_ushort(l0) |
                          ((uint32_t)__bfloat16_as_ushort(l1) << 16);
            uint32_t sw = SWZB((uint32_t)m*128 + kp*4);
            *reinterpret_cast<uint32_t*>(base + SC_AHI + sw) = hp;
            *reinterpret_cast<uint32_t*>(base + SC_ALO + sw) = lp;
        }
    };
    auto issueB = [&](int kk, int s) {
        uint32_t bhi = sb + s*SC_STAGE + SC_BHI;
        uint32_t blo = sb + s*SC_STAGE + SC_BLO;
        int k0 = kk*64;
#pragma unroll
        for (int e = 0; e < 6; e++) {
            int idx = t + e*256;
            int row = idx >> 3, col = idx & 7;
            uint32_t off = SWZB((uint32_t)row*128 + col*16);
            const __nv_bfloat16* rp = Bb + (size_t)row*KROW + k0 + col*8;
            cp16(bhi + off, rp);
            cp16(blo + off, rp + KHALF);
        }
        asm volatile("cp.async.commit_group;");
    };

    // one k16-step with fragment reuse across the 3 region passes
    auto kstep = [&](int s, int st) {
        uint32_t base = sb + s*SC_STAGE;
        uint32_t col = (uint32_t)(st*32 + (lane >> 4)*16);
        uint32_t ah[3][4], al[3][4], bh[3][4], bl[3][4];
#pragma unroll
        for (int mi = 0; mi < 3; mi++) {
            uint32_t row = wm*48 + mi*16 + (lane & 15);
            uint32_t sw = SWZB(row*128 + col);
            ldsm4(ah[mi], base + SC_AHI + sw);
            ldsm4(al[mi], base + SC_ALO + sw);
        }
#pragma unroll
        for (int nj = 0; nj < 3; nj++) {
            uint32_t row = wn*48 + nj*16 + (lane & 15);
            uint32_t sw = SWZB(row*128 + col);
            ldsm4(bh[nj], base + SC_BHI + sw);
            ldsm4(bl[nj], base + SC_BLO + sw);
        }
#pragma unroll
        for (int mi = 0; mi < 3; mi++)
#pragma unroll
            for (int ni = 0; ni < 6; ni++) {
                int nj = ni >> 1;
                uint32_t b0h = (ni & 1) ? bh[nj][1] : bh[nj][0];
                uint32_t b1h = (ni & 1) ? bh[nj][3] : bh[nj][2];
                uint32_t b0l = (ni & 1) ? bl[nj][1] : bl[nj][0];
                uint32_t b1l = (ni & 1) ? bl[nj][3] : bl[nj][2];
                mma_bf16(acc[mi][ni], ah[mi], b0h, b1h);   // hi*hi
                mma_bf16(acc[mi][ni], al[mi], b0h, b1h);   // lo*hi
                mma_bf16(acc[mi][ni], ah[mi], b0l, b1l);   // hi*lo
            }
    };

    // prologue: stage chunk 0 fully
    issueB(0, 0);
    prefA(0, 0); storeA(0, 0);
    prefA(0, 1); storeA(0, 1);
    asm volatile("cp.async.wait_group 0;");
    __syncthreads();

    for (int kk = 0; kk < SCHUNK; kk++) {
        int s = kk & 1;
        bool more = (kk < SCHUNK-1);
        if (more) { issueB(kk + 1, s ^ 1); prefA(kk + 1, 0); }
        kstep(s, 0);
        kstep(s, 1);
        if (more) { storeA(s ^ 1, 0); prefA(kk + 1, 1); }
        kstep(s, 2);
        kstep(s, 3);
        if (more) {
            storeA(s ^ 1, 1);
            asm volatile("cp.async.wait_group 0;");
        }
        __syncthreads();
    }

    // epilogue
    int mbase = oy*QW + wm*48 + (lane >> 2);
    int nbase = ntile*GM_N + wn*48 + (lane & 3)*2;
#pragma unroll
    for (int mi = 0; mi < 3; mi++)
#pragma unroll
        for (int ni = 0; ni < 6; ni++) {
            int m0 = mbase + mi*16;
            int nc = nbase + ni*8;
            float* r0 = g_attn + ((size_t)n*QPOS + m0)*LTOT + nc;
            float* r1 = r0 + 8*LTOT;
            *reinterpret_cast<float2*>(r0) = make_float2(acc[mi][ni][0], acc[mi][ni][1]);
            *reinterpret_cast<float2*>(r1) = make_float2(acc[mi][ni][2], acc[mi][ni][3]);
        }
}

// ---------------- softmax over 576 keys -> bf16 hi/lo attn -------------------------
__global__ void softmax_kernel() {
    int w    = threadIdx.x >> 5;
    int lane = threadIdx.x & 31;
    int gw = blockIdx.x * 8 + w;
    int n = gw / QPOS;
    float scale = 10.f / sqrtf(__int_as_float(g_maxssq[n]));
    const float* row = g_attn + (size_t)gw * LTOT;
    __nv_bfloat16* rowb = g_attnb + (size_t)gw * AK;
    float v[18];
    float m = -1e30f;
#pragma unroll
    for (int k = 0; k < 18; k++) {
        v[k] = row[lane + 32*k] * scale;
        m = fmaxf(m, v[k]);
    }
#pragma unroll
    for (int o = 16; o; o >>= 1) m = fmaxf(m, __shfl_xor_sync(0xffffffffu, m, o));
    float s = 0.f;
#pragma unroll
    for (int k = 0; k < 18; k++) { v[k] = __expf(v[k] - m); s += v[k]; }
#pragma unroll
    for (int o = 16; o; o >>= 1) s += __shfl_xor_sync(0xffffffffu, s, o);
    float inv = 1.f / s;
#pragma unroll
    for (int k = 0; k < 18; k++) {
        float val = v[k] * inv;
        __nv_bfloat16 h = __float2bfloat16(val);
        rowb[lane + 32*k] = h;
        rowb[LTOT + lane + 32*k] = __float2bfloat16(val - __bfloat162float(h));
    }
}

// ---------------- out GEMM: out2[m][200] = attn[m][:] x vb^T ------------------------
__global__ void __launch_bounds__(256, 1) out_mma() {
    extern __shared__ __align__(1024) char smem[];
    const int t = threadIdx.x, lane = t & 31, wid = t >> 5;
    const int wm = wid >> 1, wn = wid & 1;
    const int mtile = blockIdx.x, n = blockIdx.z;
    const uint32_t sb = smem_u32(smem);

    const __nv_bfloat16* Abase = g_attnb + ((size_t)n*QPOS + mtile*G2_M)*AK;
    const __nv_bfloat16* Bbase = g_vb + (size_t)n*G2_N*AK;

    float acc[2][16][4];
#pragma unroll
    for (int a = 0; a < 2; a++)
#pragma unroll
        for (int b = 0; b < 16; b++)
#pragma unroll
            for (int c = 0; c < 4; c++) acc[a][b][c] = 0.f;

    auto issue_chunk = [&](int kk, int s) {
        int ka, kb;
        if (kk < 9)       { ka = kk*64;                kb = kk*64; }
        else if (kk < 18) { ka = LTOT + (kk-9)*64;     kb = (kk-9)*64; }
        else              { ka = (kk-18)*64;           kb = LTOT + (kk-18)*64; }
        uint32_t As = sb + s*G2_STAGE;
        uint32_t Bs = As + G2_SMA;
#pragma unroll
        for (int e = 0; e < 4; e++) {
            int idx = t + e*256;
            int row = idx >> 3, col = idx & 7;
            uint32_t off = (uint32_t)row*128 + col*16;
            cp16(As + SWZB(off), Abase + (size_t)row*AK + ka + col*8);
        }
#pragma unroll
        for (int e = 0; e < 8; e++) {
            int idx = t + e*256;
            int row = idx >> 3, col = idx & 7;
            uint32_t off = (uint32_t)row*128 + col*16;
            cp16(Bs + SWZB(off), Bbase + (size_t)row*AK + kb + col*8);
        }
        asm volatile("cp.async.commit_group;");
    };

    issue_chunk(0, 0);
    asm volatile("cp.async.wait_group 0;");
    __syncthreads();

    for (int kk = 0; kk < G2_NCHUNK; kk++) {
        int s = kk & 1;
        if (kk < G2_NCHUNK-1) issue_chunk(kk + 1, s ^ 1);

        uint32_t As = sb + s*G2_STAGE;
        uint32_t Bs = As + G2_SMA;
#pragma unroll
        for (int st = 0; st < 4; st++) {
            int kbyte = st*32 + (lane >> 4)*16;
            uint32_t a[2][4];
#pragma unroll
            for (int mi = 0; mi < 2; mi++) {
                uint32_t off = (uint32_t)(wm*32 + mi*16 + (lane & 15))*128 + kbyte;
                ldsm4(a[mi], As + SWZB(off));
            }
            uint32_t b[8][4];
#pragma unroll
            for (int nj = 0; nj < 8; nj++) {
                uint32_t off = (uint32_t)(wn*128 + nj*16 + (lane & 15))*128 + kbyte;
                ldsm4(b[nj], Bs + SWZB(off));
            }
#pragma unroll
            for (int mi = 0; mi < 2; mi++)
#pragma unroll
                for (int ni = 0; ni < 16; ni++) {
                    int nj = ni >> 1;
                    if (ni & 1) mma_bf16(acc[mi][ni], a[mi], b[nj][1], b[nj][3]);
                    else        mma_bf16(acc[mi][ni], a[mi], b[nj][0], b[nj][2]);
                }
        }
        if (kk < G2_NCHUNK-1) asm volatile("cp.async.wait_group 0;");
        __syncthreads();
    }

    int mbase = mtile*G2_M + wm*32 + (lane >> 2);
    int nbase = wn*128 + (lane & 3)*2;
#pragma unroll
    for (int mi = 0; mi < 2; mi++)
#pragma unroll
        for (int ni = 0; ni < 16; ni++) {
            int m0 = mbase + mi*16;
            int nc = nbase + ni*8;
            float* r0 = g_out2 + ((size_t)n*QPOS + m0)*G2_N + nc;
            float* r1 = r0 + 8*G2_N;
            *reinterpret_cast<float2*>(r0) = make_float2(acc[mi][ni][0], acc[mi][ni][1]);
            *reinterpret_cast<float2*>(r1) = make_float2(acc[mi][ni][2], acc[mi][ni][3]);
        }
}

// ---------------- scatter: out2 -> res (conv_transpose geometry) --------------------
__global__ void scatter_out() {
    int idx = blockIdx.x * 256 + threadIdx.x;
    int n = blockIdx.y;
    if (idx >= HQP*HQP) return;
    int y = idx / HQP, x = idx % HQP;
    int oyA = y >> 2, iA = y & 3;  bool vA = oyA < QW;
    int oyB = oyA - 1;             bool vB = (iA == 0) && (oyB >= 0);
    int oxA = x >> 2, jA = x & 3;  bool hA = oxA < QW;
    int oxB = oxA - 1;             bool hB = (jA == 0) && (oxB >= 0);

    float acc[BAND];
#pragma unroll
    for (int b = 0; b < BAND; b++) acc[b] = 0.f;

    const float* base = g_out2 + (size_t)n*QPOS*G2_N;
#pragma unroll
    for (int ti = 0; ti < 2; ti++) {
        bool vi = ti ? vB : vA;
        if (!vi) continue;
        int oy = ti ? oyB : oyA;
        int ii = ti ? 4 : iA;
#pragma unroll
        for (int tj = 0; tj < 2; tj++) {
            bool vj = tj ? hB : hA;
            if (!vj) continue;
            int ox = tj ? oxB : oxA;
            int jj = tj ? 4 : jA;
            const float* row = base + (size_t)(oy*QW + ox)*G2_N + ii*5 + jj;
#pragma unroll
            for (int b = 0; b < BAND; b++) acc[b] += __ldg(&row[b*PP]);
        }
    }
#pragma unroll
    for (int b = 0; b < BAND; b++)
        g_res[(((size_t)n*BAND + b)*HQP + y)*HQP + x] = acc[b] * (1.f/6.f);
}

// ---------------- launch -----------------------------------------------------------
extern "C" void kernel_launch(void* const* d_in, const int* in_sizes, int n_in,
                              void* d_out, int out_size) {
    const float* ms   = (const float*)d_in[0];
    const float* pan  = (const float*)d_in[1];
    const float* pan2 = (const float*)d_in[2];
    const float* wq = (const float*)d_in[3];
    const float* bq = (const float*)d_in[4];
    const float* wk = (const float*)d_in[5];
    const float* bk = (const float*)d_in[6];
    const float* wv = (const float*)d_in[7];
    const float* bv = (const float*)d_in[8];
    const float* wr = (const float*)d_in[9];
    const float* br = (const float*)d_in[10];
    float* out = (float*)d_out;

    void* pv;
    cudaGetSymbolAddress(&pv, g_kfea); float* kfea = (float*)pv;
    cudaGetSymbolAddress(&pv, g_qfea); float* qfea = (float*)pv;
    cudaGetSymbolAddress(&pv, g_vfea); float* vfea = (float*)pv;
    cudaGetSymbolAddress(&pv, g_res);  float* res  = (float*)pv;

    cudaFuncSetAttribute(scores_mma, cudaFuncAttributeMaxDynamicSharedMemorySize, SC_TOTAL);
    cudaFuncSetAttribute(out_mma,    cudaFuncAttributeMaxDynamicSharedMemorySize, G2_TOTAL);

    // 1-3: q features, k features, keys bf16
    conv_1toC<MID, HQ, HQP> <<<dim3((HQP*HQP + 255)/256, NB), 256>>>(pan,  wq, bq, qfea);
    conv_1toC<MID, HS, HS>  <<<dim3((HS*HS   + 255)/256, NB), 256>>>(pan2, wk, bk, kfea);
    build_b_direct<<<NB*MID, LTOT>>>();

    // 4: the big one (profiled slot)
    scores_mma<<<dim3(LTOT/GM_N, QW, NB), 256, SC_TOTAL>>>();

    // v features + patches, norm scale
    conv_CtoC_all<BAND, HS><<<dim3((HS*HS + 255)/256, NB), 256>>>(ms, wv, bv, vfea);
    gather_v<<<NB*BAND*PP, LTOT>>>();
    ssq_b<<<NB*LTOT, 128>>>();

    // softmax + output GEMM + scatter
    softmax_kernel<<<NB*QPOS/8, 256>>>();
    out_mma<<<dim3(QPOS/G2_M, 1, NB), 256, G2_TOTAL>>>();
    scatter_out<<<dim3((HQP*HQP + 255)/256, NB), 256>>>();

    // final conv
    conv_CtoC_all<BAND, HQP><<<dim3((HQP*HQP + 255)/256, NB), 256>>>(res, wr, br, out);
}